// round 1
// baseline (speedup 1.0000x reference)
#include <cuda_runtime.h>
#include <cuda_bf16.h>
#include <math.h>

// Problem-fixed dimensions
#define ND   128        // input feature dim
#define H1D  64         // layer-1 output dim
#define H2D  128        // layer-2 output dim
#define NG   64         // number of graphs
#define MAXN 50000
#define MAXE 1600000
#define MAXET (MAXE + MAXN)
#define NEG_SLOPE 0.2f

// ---------------- scratch (static device globals; no allocs) ----------------
__device__ __align__(16) float d_h1[MAXN * H1D];
__device__ __align__(16) float d_g1[MAXN * H1D];
__device__ __align__(16) float d_y1[MAXN * H1D];
__device__ __align__(16) float d_h2[MAXN * H2D];
__device__ __align__(16) float d_g2[MAXN * H2D];
__device__ float d_as[MAXN];
__device__ float d_ad[MAXN];
__device__ float d_e[MAXET];
__device__ int   d_m[MAXN];
__device__ float d_den[MAXN];
__device__ __align__(16) float d_pool[NG * H2D];
__device__ float d_cnt[NG];
__device__ int   d_flag_e64;   // 1 if edge_index is int64
__device__ int   d_flag_b64;   // 1 if batch is int64

// ---------------- helpers ----------------
__device__ __forceinline__ void red_add4(float* p, float a, float b, float c, float d) {
    asm volatile("red.global.add.v4.f32 [%0], {%1,%2,%3,%4};"
                 :: "l"(p), "f"(a), "f"(b), "f"(c), "f"(d) : "memory");
}

__device__ __forceinline__ void load_edge(const void* ei, int i, int E, int is64, int& s, int& d) {
    if (is64) {
        const long long* p = (const long long*)ei;
        s = (int)p[i];
        d = (int)p[E + i];
    } else {
        const int* p = (const int*)ei;
        s = p[i];
        d = p[E + i];
    }
}

__device__ __forceinline__ int enc_ord(float v) {
    int iv = __float_as_int(v);
    return iv >= 0 ? iv : (iv ^ 0x7FFFFFFF);
}
__device__ __forceinline__ float dec_ord(int iv) {
    return iv >= 0 ? __int_as_float(iv) : __int_as_float(iv ^ 0x7FFFFFFF);
}

// ---------------- dtype detection (deterministic, per-call) ----------------
__global__ void detect_kernel(const void* ei, const void* batch, int E, int N) {
    // edge_index: if it is really int32, reading as int64 packs two random
    // node ids -> value >= 2^32 unless the high word happens to be 0.
    const long long* p = (const long long*)ei;
    int e64 = 1;
    for (int i = 0; i < 64; i++) {
        long long v = p[i];
        if (v < 0 || v >= (long long)N) { e64 = 0; break; }
    }
    d_flag_e64 = e64;
    // batch (sorted 0..63): check near the middle of the int32 interpretation
    // range; mid-array high words are ~32 -> huge when misread as int64.
    const long long* q = (const long long*)batch;
    int b64 = 1;
    int base = N / 2 - 64;
    for (int i = 0; i < 64; i++) {
        long long v = q[base + i];
        if (v < 0 || v >= NG) { b64 = 0; break; }
    }
    d_flag_b64 = b64;
}

// ---------------- init m/den ----------------
__global__ void init_md(int N) {
    int i = blockIdx.x * blockDim.x + threadIdx.x;
    if (i < N) { d_m[i] = INT_MIN; d_den[i] = 0.0f; }
}

// ---------------- GEMM1: h1 = x @ W1  (N x 128) @ (128 x 64) ----------------
__global__ void gemm1_kernel(const float* __restrict__ x, const float* __restrict__ W, int N) {
    __shared__ float Ws[ND * H1D];        // 32 KB
    __shared__ float xs[32][ND];          // 16 KB
    int tid = threadIdx.x;                // 256 threads
    for (int i = tid; i < ND * H1D; i += 256) Ws[i] = W[i];
    int n0 = blockIdx.x * 32;
    for (int i = tid; i < 32 * ND; i += 256) {
        int r = i / ND, c = i % ND;
        int n = n0 + r;
        xs[r][c] = (n < N) ? x[(size_t)n * ND + c] : 0.0f;
    }
    __syncthreads();
    int f = tid % H1D;
    int rs = tid / H1D;                   // 0..3
    for (int r = rs; r < 32; r += 4) {
        int n = n0 + r;
        if (n >= N) break;
        float acc = 0.0f;
        #pragma unroll 16
        for (int k = 0; k < ND; k++) acc += xs[r][k] * Ws[k * H1D + f];
        d_h1[(size_t)n * H1D + f] = acc;
    }
}

// ---------------- GEMM2: h2 = y1 @ W2  (N x 64) @ (64 x 128) ----------------
__global__ void gemm2_kernel(const float* __restrict__ W, int N) {
    __shared__ float Ws[H1D * H2D];       // 32 KB
    __shared__ float ys[32][H1D];         // 8 KB
    int tid = threadIdx.x;                // 256 threads
    for (int i = tid; i < H1D * H2D; i += 256) Ws[i] = W[i];
    int n0 = blockIdx.x * 32;
    for (int i = tid; i < 32 * H1D; i += 256) {
        int r = i / H1D, c = i % H1D;
        int n = n0 + r;
        ys[r][c] = (n < N) ? d_y1[(size_t)n * H1D + c] : 0.0f;
    }
    __syncthreads();
    int f = tid % H2D;
    int rs = tid / H2D;                   // 0..1
    for (int r = rs; r < 32; r += 2) {
        int n = n0 + r;
        if (n >= N) break;
        float acc = 0.0f;
        #pragma unroll 16
        for (int k = 0; k < H1D; k++) acc += ys[r][k] * Ws[k * H2D + f];
        d_h2[(size_t)n * H2D + f] = acc;
    }
}

// ---------------- per-node attention coefficients ----------------
__global__ void alphas_kernel(const float* __restrict__ h,
                              const float* __restrict__ avs, const float* __restrict__ avd,
                              int N, int F) {
    int gid = blockIdx.x * blockDim.x + threadIdx.x;
    int w = gid >> 5;
    int lane = gid & 31;
    if (w >= N) return;
    float s = 0.0f, d = 0.0f;
    for (int k = lane; k < F; k += 32) {
        float v = h[(size_t)w * F + k];
        s += v * avs[k];
        d += v * avd[k];
    }
    #pragma unroll
    for (int o = 16; o; o >>= 1) {
        s += __shfl_xor_sync(0xFFFFFFFFu, s, o);
        d += __shfl_xor_sync(0xFFFFFFFFu, d, o);
    }
    if (lane == 0) { d_as[w] = s; d_ad[w] = d; }
}

// ---------------- edge pass 1: e + segment max ----------------
__global__ void edge_max_kernel(const void* ei, int E, int ET) {
    int i = blockIdx.x * blockDim.x + threadIdx.x;
    if (i >= ET) return;
    int is64 = d_flag_e64;
    int s, d;
    if (i < E) load_edge(ei, i, E, is64, s, d);
    else       { s = d = i - E; }
    float v = d_as[s] + d_ad[d];
    v = (v > 0.0f) ? v : NEG_SLOPE * v;
    d_e[i] = v;
    atomicMax(&d_m[d], enc_ord(v));
}

// ---------------- edge pass 2: exp + segment sum ----------------
__global__ void edge_exp_kernel(const void* ei, int E, int ET) {
    int i = blockIdx.x * blockDim.x + threadIdx.x;
    if (i >= ET) return;
    int is64 = d_flag_e64;
    int s, d;
    if (i < E) load_edge(ei, i, E, is64, s, d);
    else       { s = d = i - E; }
    float mm = dec_ord(d_m[d]);
    float ex = expf(d_e[i] - mm);
    d_e[i] = ex;
    atomicAdd(&d_den[d], ex);
}

// ---------------- edge pass 3: weighted aggregation (vectorized red) --------
template <int F>
__global__ void edge_agg_kernel(const void* ei, const float* __restrict__ h,
                                float* __restrict__ g, int E, int ET) {
    const int LPE = F / 4;     // lanes per edge (16 or 32)
    int gid = blockIdx.x * blockDim.x + threadIdx.x;
    int i = gid / LPE;
    int lane = gid % LPE;
    if (i >= ET) return;
    int is64 = d_flag_e64;
    int s, d;
    if (i < E) load_edge(ei, i, E, is64, s, d);
    else       { s = d = i - E; }
    float alpha = d_e[i] / (d_den[d] + 1e-16f);
    const float4* hp = (const float4*)(h + (size_t)s * F);
    float4 v = hp[lane];
    float* dst = g + (size_t)d * F + lane * 4;
    red_add4(dst, v.x * alpha, v.y * alpha, v.z * alpha, v.w * alpha);
}

// ---------------- finalize layer 1: y1 = relu(g1 + b1) ----------------
__global__ void finalize1_kernel(const float* __restrict__ b1, int N) {
    int idx = blockIdx.x * blockDim.x + threadIdx.x;
    if (idx >= N * H1D) return;
    float v = d_g1[idx] + b1[idx % H1D];
    d_y1[idx] = v > 0.0f ? v : 0.0f;
}

// ---------------- finalize layer 2 + pooling sum ----------------
__global__ void finalize2_pool_kernel(const float* __restrict__ b2, const void* batch, int N) {
    int idx = blockIdx.x * blockDim.x + threadIdx.x;   // N * 32 threads
    int n = idx / (H2D / 4);
    int c = idx % (H2D / 4);
    if (n >= N) return;
    int b;
    if (d_flag_b64) b = (int)((const long long*)batch)[n];
    else            b = ((const int*)batch)[n];
    const float4* gp = (const float4*)(d_g2 + (size_t)n * H2D);
    const float4* bp = (const float4*)b2;
    float4 v = gp[c], bb = bp[c];
    float a0 = fmaxf(v.x + bb.x, 0.0f);
    float a1 = fmaxf(v.y + bb.y, 0.0f);
    float a2 = fmaxf(v.z + bb.z, 0.0f);
    float a3 = fmaxf(v.w + bb.w, 0.0f);
    red_add4(d_pool + (size_t)b * H2D + c * 4, a0, a1, a2, a3);
}

__global__ void counts_kernel(const void* batch, int N) {
    int n = blockIdx.x * blockDim.x + threadIdx.x;
    if (n >= N) return;
    int b;
    if (d_flag_b64) b = (int)((const long long*)batch)[n];
    else            b = ((const int*)batch)[n];
    atomicAdd(&d_cnt[b], 1.0f);
}

// ---------------- FC: out = (pool/cnt) @ Wfc + bfc ----------------
__global__ void fc_kernel(const float* __restrict__ Wfc, const float* __restrict__ bfc,
                          float* __restrict__ out) {
    __shared__ float p[H2D];
    int g = blockIdx.x;      // 64 graphs
    int f = threadIdx.x;     // 64 out features
    float cnt = fmaxf(d_cnt[g], 1.0f);
    for (int k = f; k < H2D; k += 64) p[k] = d_pool[g * H2D + k] / cnt;
    __syncthreads();
    float acc = bfc[f];
    #pragma unroll 16
    for (int k = 0; k < H2D; k++) acc += p[k] * Wfc[k * 64 + f];
    out[g * 64 + f] = acc;
}

// ---------------- launch ----------------
static inline int cdiv(long long a, int b) { return (int)((a + b - 1) / b); }

extern "C" void kernel_launch(void* const* d_in, const int* in_sizes, int n_in,
                              void* d_out, int out_size) {
    const float* x      = (const float*)d_in[0];
    const void*  ei     = d_in[1];
    const void*  batch  = d_in[2];
    const float* W1     = (const float*)d_in[3];
    const float* a_src1 = (const float*)d_in[4];
    const float* a_dst1 = (const float*)d_in[5];
    const float* b1     = (const float*)d_in[6];
    const float* W2     = (const float*)d_in[7];
    const float* a_src2 = (const float*)d_in[8];
    const float* a_dst2 = (const float*)d_in[9];
    const float* b2     = (const float*)d_in[10];
    const float* Wfc    = (const float*)d_in[11];
    const float* bfc    = (const float*)d_in[12];
    float* out = (float*)d_out;

    const int N  = in_sizes[2];
    const int E  = in_sizes[1] / 2;
    const int ET = E + N;

    // scratch zeroing (capture-safe async memsets)
    void *pg1, *pg2, *ppool, *pcnt;
    cudaGetSymbolAddress(&pg1, d_g1);
    cudaGetSymbolAddress(&pg2, d_g2);
    cudaGetSymbolAddress(&ppool, d_pool);
    cudaGetSymbolAddress(&pcnt, d_cnt);
    cudaMemsetAsync(pg1, 0, (size_t)N * H1D * sizeof(float), 0);
    cudaMemsetAsync(pg2, 0, (size_t)N * H2D * sizeof(float), 0);
    cudaMemsetAsync(ppool, 0, NG * H2D * sizeof(float), 0);
    cudaMemsetAsync(pcnt, 0, NG * sizeof(float), 0);

    detect_kernel<<<1, 1>>>(ei, batch, E, N);
    init_md<<<cdiv(N, 256), 256>>>(N);

    // ---- layer 1 ----
    gemm1_kernel<<<cdiv(N, 32), 256>>>(x, W1, N);
    {
        float *h1p, *g1p;
        cudaGetSymbolAddress((void**)&h1p, d_h1);
        cudaGetSymbolAddress((void**)&g1p, d_g1);
        alphas_kernel<<<cdiv((long long)N * 32, 256), 256>>>(h1p, a_src1, a_dst1, N, H1D);
        edge_max_kernel<<<cdiv(ET, 256), 256>>>(ei, E, ET);
        edge_exp_kernel<<<cdiv(ET, 256), 256>>>(ei, E, ET);
        edge_agg_kernel<H1D><<<cdiv((long long)ET * (H1D / 4), 256), 256>>>(ei, h1p, g1p, E, ET);
    }
    finalize1_kernel<<<cdiv((long long)N * H1D, 256), 256>>>(b1, N);

    // ---- layer 2 ----
    init_md<<<cdiv(N, 256), 256>>>(N);
    gemm2_kernel<<<cdiv(N, 32), 256>>>(W2, N);
    {
        float *h2p, *g2p;
        cudaGetSymbolAddress((void**)&h2p, d_h2);
        cudaGetSymbolAddress((void**)&g2p, d_g2);
        alphas_kernel<<<cdiv((long long)N * 32, 256), 256>>>(h2p, a_src2, a_dst2, N, H2D);
        edge_max_kernel<<<cdiv(ET, 256), 256>>>(ei, E, ET);
        edge_exp_kernel<<<cdiv(ET, 256), 256>>>(ei, E, ET);
        edge_agg_kernel<H2D><<<cdiv((long long)ET * (H2D / 4), 256), 256>>>(ei, h2p, g2p, E, ET);
    }

    // ---- pool + fc ----
    finalize2_pool_kernel<<<cdiv((long long)N * (H2D / 4), 256), 256>>>(b2, batch, N);
    counts_kernel<<<cdiv(N, 256), 256>>>(batch, N);
    fc_kernel<<<NG, 64>>>(Wfc, bfc, out);
}

// round 2
// speedup vs baseline: 2.0075x; 2.0075x over previous
#include <cuda_runtime.h>
#include <cuda_bf16.h>
#include <math.h>

#define ND   128
#define H1D  64
#define H2D  128
#define NG   64
#define MAXN 50000
#define MAXE 1600000
#define MAXET (MAXE + MAXN)
#define NEG_SLOPE 0.2f

// ---------------- scratch ----------------
__device__ __align__(16) float d_h1[MAXN * H1D];
__device__ __align__(16) float d_y1[MAXN * H1D];
__device__ __align__(16) float d_h2[MAXN * H2D];
__device__ float d_as[MAXN];
__device__ float d_ad[MAXN];
__device__ float d_e[MAXET];          // per-edge scratch (e, then ex), CSR order
__device__ int   d_deg[MAXN];
__device__ int   d_cur[MAXN];
__device__ int   d_row[MAXN + 1];
__device__ int   d_csrc[MAXET];       // CSR src array
__device__ __align__(16) float d_pool[NG * H2D];
__device__ float d_cnt[NG];
__device__ int   d_flag_e64;
__device__ int   d_flag_b64;

// ---------------- helpers ----------------
__device__ __forceinline__ void red_add4(float* p, float a, float b, float c, float d) {
    asm volatile("red.global.add.v4.f32 [%0], {%1,%2,%3,%4};"
                 :: "l"(p), "f"(a), "f"(b), "f"(c), "f"(d) : "memory");
}

__device__ __forceinline__ void load_edge(const void* ei, int i, int E, int is64, int& s, int& d) {
    if (is64) {
        const long long* p = (const long long*)ei;
        s = (int)p[i];
        d = (int)p[E + i];
    } else {
        const int* p = (const int*)ei;
        s = p[i];
        d = p[E + i];
    }
}

// ---------------- dtype detection ----------------
__global__ void detect_kernel(const void* ei, const void* batch, int E, int N) {
    const long long* p = (const long long*)ei;
    int e64 = 1;
    for (int i = 0; i < 64; i++) {
        long long v = p[i];
        if (v < 0 || v >= (long long)N) { e64 = 0; break; }
    }
    d_flag_e64 = e64;
    const long long* q = (const long long*)batch;
    int b64 = 1;
    int base = N / 2 - 64;
    for (int i = 0; i < 64; i++) {
        long long v = q[base + i];
        if (v < 0 || v >= NG) { b64 = 0; break; }
    }
    d_flag_b64 = b64;
}

// ---------------- CSR build ----------------
__global__ void init_deg_kernel(int N) {
    int i = blockIdx.x * blockDim.x + threadIdx.x;
    if (i < N) d_deg[i] = 1;   // self loop
}

__global__ void hist_kernel(const void* ei, int E) {
    int i = blockIdx.x * blockDim.x + threadIdx.x;
    if (i >= E) return;
    int is64 = d_flag_e64;
    int s, d;
    load_edge(ei, i, E, is64, s, d);
    atomicAdd(&d_deg[d], 1);
}

__global__ void scan_kernel(int N) {   // single block, 1024 threads
    __shared__ int sums[1024];
    int t = threadIdx.x;
    int C = (N + 1023) / 1024;
    int s = 0;
    for (int k = 0; k < C; k++) {
        int idx = t * C + k;
        if (idx < N) s += d_deg[idx];
    }
    sums[t] = s;
    __syncthreads();
    for (int off = 1; off < 1024; off <<= 1) {
        int v = (t >= off) ? sums[t - off] : 0;
        __syncthreads();
        sums[t] += v;
        __syncthreads();
    }
    int run = (t == 0) ? 0 : sums[t - 1];
    for (int k = 0; k < C; k++) {
        int idx = t * C + k;
        if (idx < N) { d_row[idx] = run; run += d_deg[idx]; }
    }
    if (t == 0) d_row[N] = sums[1023];
}

__global__ void selfloop_kernel(int N) {
    int i = blockIdx.x * blockDim.x + threadIdx.x;
    if (i >= N) return;
    int p = d_row[i];
    d_csrc[p] = i;
    d_cur[i] = p + 1;
}

__global__ void scatter_kernel(const void* ei, int E) {
    int i = blockIdx.x * blockDim.x + threadIdx.x;
    if (i >= E) return;
    int is64 = d_flag_e64;
    int s, d;
    load_edge(ei, i, E, is64, s, d);
    int p = atomicAdd(&d_cur[d], 1);
    d_csrc[p] = s;
}

// ---------------- tiled GEMM: C[N,OUT] = A[N,K] @ W[K,OUT] ----------------
template <int K, int OUT>
__global__ void gemm_tiled(const float* __restrict__ A, const float* __restrict__ W,
                           float* __restrict__ C, int N) {
    const int CPT = OUT / 16;            // cols per thread (4 or 8)
    __shared__ float As[64][33];
    __shared__ float Ws[32][OUT];
    float acc[4][CPT];
    #pragma unroll
    for (int i = 0; i < 4; i++)
        #pragma unroll
        for (int j = 0; j < CPT; j++) acc[i][j] = 0.0f;

    int tx = threadIdx.x % 16, ty = threadIdx.x / 16;
    int row0 = blockIdx.x * 64;

    for (int kk = 0; kk < K; kk += 32) {
        for (int i = threadIdx.x; i < 64 * 32; i += 256) {
            int r = i / 32, c = i % 32;
            int gr = row0 + r;
            As[r][c] = (gr < N) ? A[(size_t)gr * K + kk + c] : 0.0f;
        }
        for (int i = threadIdx.x; i < 32 * OUT; i += 256) {
            int r = i / OUT, c = i % OUT;
            Ws[r][c] = W[(size_t)(kk + r) * OUT + c];
        }
        __syncthreads();
        #pragma unroll
        for (int k = 0; k < 32; k++) {
            float a[4], w[CPT];
            #pragma unroll
            for (int i = 0; i < 4; i++) a[i] = As[ty * 4 + i][k];
            #pragma unroll
            for (int j = 0; j < CPT; j++) w[j] = Ws[k][j * 16 + tx];
            #pragma unroll
            for (int i = 0; i < 4; i++)
                #pragma unroll
                for (int j = 0; j < CPT; j++) acc[i][j] += a[i] * w[j];
        }
        __syncthreads();
    }
    #pragma unroll
    for (int i = 0; i < 4; i++) {
        int r = row0 + ty * 4 + i;
        if (r >= N) break;
        #pragma unroll
        for (int j = 0; j < CPT; j++)
            C[(size_t)r * OUT + j * 16 + tx] = acc[i][j];
    }
}

// ---------------- per-node attention coefficients ----------------
__global__ void alphas_kernel(const float* __restrict__ h,
                              const float* __restrict__ avs, const float* __restrict__ avd,
                              int N, int F) {
    int gid = blockIdx.x * blockDim.x + threadIdx.x;
    int w = gid >> 5;
    int lane = gid & 31;
    if (w >= N) return;
    float s = 0.0f, d = 0.0f;
    for (int k = lane; k < F; k += 32) {
        float v = h[(size_t)w * F + k];
        s += v * avs[k];
        d += v * avd[k];
    }
    #pragma unroll
    for (int o = 16; o; o >>= 1) {
        s += __shfl_xor_sync(0xFFFFFFFFu, s, o);
        d += __shfl_xor_sync(0xFFFFFFFFu, d, o);
    }
    if (lane == 0) { d_as[w] = s; d_ad[w] = d; }
}

// ---------------- fused GAT aggregation: warp per dst node ----------------
// pass1: e = leaky(as[s]+ad[d]), store, warp-max
// pass2: ex = exp(e-m), store, warp-sum den
// pass3: acc = sum ex_j * h[src_j]  (registers), epilogue: relu(acc*inv + b)
// DO_POOL: layer 2 — also red.add into d_pool instead of storing y.
template <int F, int DO_POOL>
__global__ void gat_kernel(const float* __restrict__ h, const float* __restrict__ bias,
                           float* __restrict__ y, const void* batch, int N) {
    int w = (blockIdx.x * blockDim.x + threadIdx.x) >> 5;
    int lane = threadIdx.x & 31;
    if (w >= N) return;
    int beg = d_row[w], end = d_row[w + 1];
    float ad_d = d_ad[w];

    // pass 1: e + max
    float m = -INFINITY;
    for (int j = beg + lane; j < end; j += 32) {
        int s = d_csrc[j];
        float e = d_as[s] + ad_d;
        e = (e > 0.0f) ? e : NEG_SLOPE * e;
        d_e[j] = e;
        m = fmaxf(m, e);
    }
    #pragma unroll
    for (int o = 16; o; o >>= 1) m = fmaxf(m, __shfl_xor_sync(0xFFFFFFFFu, m, o));

    // pass 2: exp + den
    float den = 0.0f;
    for (int j = beg + lane; j < end; j += 32) {
        float ex = __expf(d_e[j] - m);
        d_e[j] = ex;
        den += ex;
    }
    #pragma unroll
    for (int o = 16; o; o >>= 1) den += __shfl_xor_sync(0xFFFFFFFFu, den, o);
    float inv = 1.0f / (den + 1e-16f);

    // pass 3: feature aggregation (registers)
    if (F == 128) {
        float4 acc = make_float4(0.f, 0.f, 0.f, 0.f);
        int j = beg;
        for (; j + 4 <= end; j += 4) {
            int s0 = d_csrc[j], s1 = d_csrc[j + 1], s2 = d_csrc[j + 2], s3 = d_csrc[j + 3];
            float a0 = d_e[j], a1 = d_e[j + 1], a2 = d_e[j + 2], a3 = d_e[j + 3];
            float4 v0 = *(const float4*)(h + (size_t)s0 * F + lane * 4);
            float4 v1 = *(const float4*)(h + (size_t)s1 * F + lane * 4);
            float4 v2 = *(const float4*)(h + (size_t)s2 * F + lane * 4);
            float4 v3 = *(const float4*)(h + (size_t)s3 * F + lane * 4);
            acc.x += a0 * v0.x + a1 * v1.x + a2 * v2.x + a3 * v3.x;
            acc.y += a0 * v0.y + a1 * v1.y + a2 * v2.y + a3 * v3.y;
            acc.z += a0 * v0.z + a1 * v1.z + a2 * v2.z + a3 * v3.z;
            acc.w += a0 * v0.w + a1 * v1.w + a2 * v2.w + a3 * v3.w;
        }
        for (; j < end; j++) {
            int s = d_csrc[j];
            float a = d_e[j];
            float4 v = *(const float4*)(h + (size_t)s * F + lane * 4);
            acc.x += a * v.x; acc.y += a * v.y; acc.z += a * v.z; acc.w += a * v.w;
        }
        const float4 bb = *(const float4*)(bias + lane * 4);
        float r0 = fmaxf(acc.x * inv + bb.x, 0.0f);
        float r1 = fmaxf(acc.y * inv + bb.y, 0.0f);
        float r2 = fmaxf(acc.z * inv + bb.z, 0.0f);
        float r3 = fmaxf(acc.w * inv + bb.w, 0.0f);
        if (DO_POOL) {
            int b;
            if (d_flag_b64) b = (int)((const long long*)batch)[w];
            else            b = ((const int*)batch)[w];
            red_add4(d_pool + (size_t)b * H2D + lane * 4, r0, r1, r2, r3);
        } else {
            *(float4*)(y + (size_t)w * F + lane * 4) = make_float4(r0, r1, r2, r3);
        }
    } else { // F == 64: two half-warps, each handles alternating edges
        int sub = lane >> 4;       // 0 or 1
        int l2  = lane & 15;
        float4 acc = make_float4(0.f, 0.f, 0.f, 0.f);
        int j = beg + sub;
        for (; j + 2 < end; j += 4) {
            int s0 = d_csrc[j], s1 = d_csrc[j + 2];
            float a0 = d_e[j], a1 = d_e[j + 2];
            float4 v0 = *(const float4*)(h + (size_t)s0 * F + l2 * 4);
            float4 v1 = *(const float4*)(h + (size_t)s1 * F + l2 * 4);
            acc.x += a0 * v0.x + a1 * v1.x;
            acc.y += a0 * v0.y + a1 * v1.y;
            acc.z += a0 * v0.z + a1 * v1.z;
            acc.w += a0 * v0.w + a1 * v1.w;
        }
        for (; j < end; j += 2) {
            int s = d_csrc[j];
            float a = d_e[j];
            float4 v = *(const float4*)(h + (size_t)s * F + l2 * 4);
            acc.x += a * v.x; acc.y += a * v.y; acc.z += a * v.z; acc.w += a * v.w;
        }
        // combine the two halves
        acc.x += __shfl_down_sync(0xFFFFFFFFu, acc.x, 16);
        acc.y += __shfl_down_sync(0xFFFFFFFFu, acc.y, 16);
        acc.z += __shfl_down_sync(0xFFFFFFFFu, acc.z, 16);
        acc.w += __shfl_down_sync(0xFFFFFFFFu, acc.w, 16);
        if (lane < 16) {
            const float4 bb = *(const float4*)(bias + l2 * 4);
            float4 r;
            r.x = fmaxf(acc.x * inv + bb.x, 0.0f);
            r.y = fmaxf(acc.y * inv + bb.y, 0.0f);
            r.z = fmaxf(acc.z * inv + bb.z, 0.0f);
            r.w = fmaxf(acc.w * inv + bb.w, 0.0f);
            *(float4*)(y + (size_t)w * F + l2 * 4) = r;
        }
    }
}

__global__ void counts_kernel(const void* batch, int N) {
    int n = blockIdx.x * blockDim.x + threadIdx.x;
    if (n >= N) return;
    int b;
    if (d_flag_b64) b = (int)((const long long*)batch)[n];
    else            b = ((const int*)batch)[n];
    atomicAdd(&d_cnt[b], 1.0f);
}

__global__ void fc_kernel(const float* __restrict__ Wfc, const float* __restrict__ bfc,
                          float* __restrict__ out) {
    __shared__ float p[H2D];
    int g = blockIdx.x;
    int f = threadIdx.x;
    float cnt = fmaxf(d_cnt[g], 1.0f);
    for (int k = f; k < H2D; k += 64) p[k] = d_pool[g * H2D + k] / cnt;
    __syncthreads();
    float acc = bfc[f];
    #pragma unroll 16
    for (int k = 0; k < H2D; k++) acc += p[k] * Wfc[k * 64 + f];
    out[g * 64 + f] = acc;
}

// ---------------- launch ----------------
static inline int cdiv(long long a, int b) { return (int)((a + b - 1) / b); }

extern "C" void kernel_launch(void* const* d_in, const int* in_sizes, int n_in,
                              void* d_out, int out_size) {
    const float* x      = (const float*)d_in[0];
    const void*  ei     = d_in[1];
    const void*  batch  = d_in[2];
    const float* W1     = (const float*)d_in[3];
    const float* a_src1 = (const float*)d_in[4];
    const float* a_dst1 = (const float*)d_in[5];
    const float* b1     = (const float*)d_in[6];
    const float* W2     = (const float*)d_in[7];
    const float* a_src2 = (const float*)d_in[8];
    const float* a_dst2 = (const float*)d_in[9];
    const float* b2     = (const float*)d_in[10];
    const float* Wfc    = (const float*)d_in[11];
    const float* bfc    = (const float*)d_in[12];
    float* out = (float*)d_out;

    const int N = in_sizes[2];
    const int E = in_sizes[1] / 2;

    void *ppool, *pcnt;
    cudaGetSymbolAddress(&ppool, d_pool);
    cudaGetSymbolAddress(&pcnt, d_cnt);
    cudaMemsetAsync(ppool, 0, NG * H2D * sizeof(float), 0);
    cudaMemsetAsync(pcnt, 0, NG * sizeof(float), 0);

    detect_kernel<<<1, 1>>>(ei, batch, E, N);

    // CSR build (shared by both layers)
    init_deg_kernel<<<cdiv(N, 256), 256>>>(N);
    hist_kernel<<<cdiv(E, 256), 256>>>(ei, E);
    scan_kernel<<<1, 1024>>>(N);
    selfloop_kernel<<<cdiv(N, 256), 256>>>(N);
    scatter_kernel<<<cdiv(E, 256), 256>>>(ei, E);

    float *h1p, *y1p, *h2p;
    cudaGetSymbolAddress((void**)&h1p, d_h1);
    cudaGetSymbolAddress((void**)&y1p, d_y1);
    cudaGetSymbolAddress((void**)&h2p, d_h2);

    // ---- layer 1 ----
    gemm_tiled<ND, H1D><<<cdiv(N, 64), 256>>>(x, W1, h1p, N);
    alphas_kernel<<<cdiv((long long)N * 32, 256), 256>>>(h1p, a_src1, a_dst1, N, H1D);
    gat_kernel<H1D, 0><<<cdiv(N, 8), 256>>>(h1p, b1, y1p, batch, N);

    // ---- layer 2 (pooling fused into epilogue) ----
    gemm_tiled<H1D, H2D><<<cdiv(N, 64), 256>>>(y1p, W2, h2p, N);
    alphas_kernel<<<cdiv((long long)N * 32, 256), 256>>>(h2p, a_src2, a_dst2, N, H2D);
    gat_kernel<H2D, 1><<<cdiv(N, 8), 256>>>(h2p, b2, nullptr, batch, N);

    // ---- mean + fc ----
    counts_kernel<<<cdiv(N, 256), 256>>>(batch, N);
    fc_kernel<<<NG, 64>>>(Wfc, bfc, out);
}

// round 3
// speedup vs baseline: 2.3674x; 1.1792x over previous
#include <cuda_runtime.h>
#include <cuda_bf16.h>
#include <math.h>

#define ND   128
#define H1D  64
#define H2D  128
#define NG   64
#define MAXN 50000
#define MAXE 1600000
#define MAXET (MAXE + MAXN)
#define NEG_SLOPE 0.2f
#define NBLK 64            // >= ceil(MAXN/1024)

// ---------------- scratch ----------------
__device__ __align__(16) float d_h1[MAXN * H1D];
__device__ __align__(16) float d_y1[MAXN * H1D];
__device__ __align__(16) float d_h2[MAXN * H2D];
__device__ float d_as[MAXN];
__device__ float d_ad[MAXN];
__device__ float d_e[MAXET];
__device__ int   d_deg[MAXN];
__device__ int   d_cur[MAXN];
__device__ int   d_row[MAXN + 1];
__device__ int   d_csrc[MAXET];
__device__ int   d_bsum[NBLK];
__device__ int   d_bpre[NBLK];
__device__ __align__(16) float d_pool[NG * H2D];
__device__ float d_cnt[NG];
__device__ int   d_flag_e64;
__device__ int   d_flag_b64;

// ---------------- helpers ----------------
__device__ __forceinline__ void red_add4(float* p, float a, float b, float c, float d) {
    asm volatile("red.global.add.v4.f32 [%0], {%1,%2,%3,%4};"
                 :: "l"(p), "f"(a), "f"(b), "f"(c), "f"(d) : "memory");
}

__device__ __forceinline__ void load_edge(const void* ei, int i, int E, int is64, int& s, int& d) {
    if (is64) {
        const long long* p = (const long long*)ei;
        s = (int)p[i];
        d = (int)p[E + i];
    } else {
        const int* p = (const int*)ei;
        s = p[i];
        d = p[E + i];
    }
}

// ---------------- dtype detection (parallel) ----------------
__global__ void detect_kernel(const void* ei, const void* batch, int E, int N) {
    __shared__ int se, sb;
    int t = threadIdx.x;                // 128 threads
    if (t == 0) { se = 1; sb = 1; }
    __syncthreads();
    if (t < 64) {
        long long v = ((const long long*)ei)[t];
        if (v < 0 || v >= (long long)N) atomicAnd(&se, 0);
    } else {
        int base = N / 2 - 64;
        long long v = ((const long long*)batch)[base + (t - 64)];
        if (v < 0 || v >= NG) atomicAnd(&sb, 0);
    }
    __syncthreads();
    if (t == 0) { d_flag_e64 = se; d_flag_b64 = sb; }
}

// ---------------- CSR build ----------------
__global__ void init_deg_kernel(int N) {
    int i = blockIdx.x * blockDim.x + threadIdx.x;
    if (i < N) d_deg[i] = 1;   // self loop
}

__global__ void hist_kernel(const void* ei, int E) {
    int i = blockIdx.x * blockDim.x + threadIdx.x;
    if (i >= E) return;
    int is64 = d_flag_e64;
    int s, d;
    load_edge(ei, i, E, is64, s, d);
    atomicAdd(&d_deg[d], 1);
}

// phase 1: per-block (1024 elems) sums
__global__ void block_reduce_kernel(int N) {
    __shared__ int sm[256];
    int b = blockIdx.x, t = threadIdx.x;
    int base = b * 1024 + t * 4;
    int s = 0;
    #pragma unroll
    for (int k = 0; k < 4; k++) { int i = base + k; if (i < N) s += d_deg[i]; }
    sm[t] = s;
    __syncthreads();
    for (int off = 128; off; off >>= 1) {
        if (t < off) sm[t] += sm[t + off];
        __syncthreads();
    }
    if (t == 0) d_bsum[b] = sm[0];
}

// phase 2: scan the (<=64) block sums; also writes d_row[N]
__global__ void scan_bsum_kernel(int B, int N) {
    __shared__ int sm[128];
    int t = threadIdx.x;                // 128
    int v = (t < B) ? d_bsum[t] : 0;
    sm[t] = v;
    __syncthreads();
    for (int off = 1; off < 128; off <<= 1) {
        int u = (t >= off) ? sm[t - off] : 0;
        __syncthreads();
        sm[t] += u;
        __syncthreads();
    }
    if (t < B) d_bpre[t] = sm[t] - v;   // exclusive prefix
    if (t == 127) d_row[N] = sm[127];
}

// phase 3: per-block exclusive scan + global prefix -> d_row
__global__ void block_scan_kernel(int N) {
    __shared__ int sm[256];
    int b = blockIdx.x, t = threadIdx.x;
    int base = b * 1024 + t * 4;
    int v[4], pre[4];
    int s = 0;
    #pragma unroll
    for (int k = 0; k < 4; k++) {
        int i = base + k;
        v[k] = (i < N) ? d_deg[i] : 0;
        pre[k] = s;
        s += v[k];
    }
    sm[t] = s;
    __syncthreads();
    for (int off = 1; off < 256; off <<= 1) {
        int u = (t >= off) ? sm[t - off] : 0;
        __syncthreads();
        sm[t] += u;
        __syncthreads();
    }
    int prefix = d_bpre[b] + (sm[t] - s);
    #pragma unroll
    for (int k = 0; k < 4; k++) {
        int i = base + k;
        if (i < N) d_row[i] = prefix + pre[k];
    }
}

__global__ void selfloop_kernel(int N) {
    int i = blockIdx.x * blockDim.x + threadIdx.x;
    if (i >= N) return;
    int p = d_row[i];
    d_csrc[p] = i;
    d_cur[i] = p + 1;
}

__global__ void scatter_kernel(const void* ei, int E) {
    int i = blockIdx.x * blockDim.x + threadIdx.x;
    if (i >= E) return;
    int is64 = d_flag_e64;
    int s, d;
    load_edge(ei, i, E, is64, s, d);
    int p = atomicAdd(&d_cur[d], 1);
    d_csrc[p] = s;
}

// ---------------- tiled GEMM with fused alphas ----------------
// C[N,OUT] = A[N,K] @ W[K,OUT]; also d_as[n] = C[n,:].a_src, d_ad[n] = C[n,:].a_dst
template <int K, int OUT>
__global__ void gemm_tiled(const float* __restrict__ A, const float* __restrict__ W,
                           float* __restrict__ C,
                           const float* __restrict__ avs, const float* __restrict__ avd,
                           int N) {
    const int CPT = OUT / 16;            // 4 or 8
    __shared__ float As[64][33];
    __shared__ float Ws[32][OUT];
    float acc[4][CPT];
    #pragma unroll
    for (int i = 0; i < 4; i++)
        #pragma unroll
        for (int j = 0; j < CPT; j++) acc[i][j] = 0.0f;

    int tx = threadIdx.x % 16, ty = threadIdx.x / 16;
    int row0 = blockIdx.x * 64;

    for (int kk = 0; kk < K; kk += 32) {
        for (int i = threadIdx.x; i < 64 * 32; i += 256) {
            int r = i / 32, c = i % 32;
            int gr = row0 + r;
            As[r][c] = (gr < N) ? A[(size_t)gr * K + kk + c] : 0.0f;
        }
        for (int i = threadIdx.x; i < 32 * OUT; i += 256) {
            int r = i / OUT, c = i % OUT;
            Ws[r][c] = W[(size_t)(kk + r) * OUT + c];
        }
        __syncthreads();
        #pragma unroll
        for (int k = 0; k < 32; k++) {
            float a[4], w[CPT];
            #pragma unroll
            for (int i = 0; i < 4; i++) a[i] = As[ty * 4 + i][k];
            #pragma unroll
            for (int j = 0; j < CPT; j++) w[j] = Ws[k][j * 16 + tx];
            #pragma unroll
            for (int i = 0; i < 4; i++)
                #pragma unroll
                for (int j = 0; j < CPT; j++) acc[i][j] += a[i] * w[j];
        }
        __syncthreads();
    }

    // store C
    #pragma unroll
    for (int i = 0; i < 4; i++) {
        int r = row0 + ty * 4 + i;
        if (r >= N) break;
        #pragma unroll
        for (int j = 0; j < CPT; j++)
            C[(size_t)r * OUT + j * 16 + tx] = acc[i][j];
    }

    // fused alphas: reduce acc . avs/avd across the 16 lanes sharing a row
    float vs[CPT], vd[CPT];
    #pragma unroll
    for (int j = 0; j < CPT; j++) {
        vs[j] = avs[j * 16 + tx];
        vd[j] = avd[j * 16 + tx];
    }
    #pragma unroll
    for (int i = 0; i < 4; i++) {
        float ps = 0.0f, pd = 0.0f;
        #pragma unroll
        for (int j = 0; j < CPT; j++) {
            ps += acc[i][j] * vs[j];
            pd += acc[i][j] * vd[j];
        }
        #pragma unroll
        for (int o = 8; o; o >>= 1) {
            ps += __shfl_xor_sync(0xFFFFFFFFu, ps, o);
            pd += __shfl_xor_sync(0xFFFFFFFFu, pd, o);
        }
        int r = row0 + ty * 4 + i;
        if (tx == 0 && r < N) { d_as[r] = ps; d_ad[r] = pd; }
    }
}

// ---------------- fused GAT aggregation: warp per dst node ----------------
template <int F, int DO_POOL>
__global__ void gat_kernel(const float* __restrict__ h, const float* __restrict__ bias,
                           float* __restrict__ y, const void* batch, int N) {
    int w = (blockIdx.x * blockDim.x + threadIdx.x) >> 5;
    int lane = threadIdx.x & 31;
    if (w >= N) return;
    int beg = d_row[w], end = d_row[w + 1];
    float ad_d = d_ad[w];

    float m = -INFINITY;
    for (int j = beg + lane; j < end; j += 32) {
        int s = d_csrc[j];
        float e = d_as[s] + ad_d;
        e = (e > 0.0f) ? e : NEG_SLOPE * e;
        d_e[j] = e;
        m = fmaxf(m, e);
    }
    #pragma unroll
    for (int o = 16; o; o >>= 1) m = fmaxf(m, __shfl_xor_sync(0xFFFFFFFFu, m, o));

    float den = 0.0f;
    for (int j = beg + lane; j < end; j += 32) {
        float ex = __expf(d_e[j] - m);
        d_e[j] = ex;
        den += ex;
    }
    #pragma unroll
    for (int o = 16; o; o >>= 1) den += __shfl_xor_sync(0xFFFFFFFFu, den, o);
    float inv = 1.0f / (den + 1e-16f);

    if (F == 128) {
        float4 acc = make_float4(0.f, 0.f, 0.f, 0.f);
        int j = beg;
        for (; j + 4 <= end; j += 4) {
            int s0 = d_csrc[j], s1 = d_csrc[j + 1], s2 = d_csrc[j + 2], s3 = d_csrc[j + 3];
            float a0 = d_e[j], a1 = d_e[j + 1], a2 = d_e[j + 2], a3 = d_e[j + 3];
            float4 v0 = *(const float4*)(h + (size_t)s0 * F + lane * 4);
            float4 v1 = *(const float4*)(h + (size_t)s1 * F + lane * 4);
            float4 v2 = *(const float4*)(h + (size_t)s2 * F + lane * 4);
            float4 v3 = *(const float4*)(h + (size_t)s3 * F + lane * 4);
            acc.x += a0 * v0.x + a1 * v1.x + a2 * v2.x + a3 * v3.x;
            acc.y += a0 * v0.y + a1 * v1.y + a2 * v2.y + a3 * v3.y;
            acc.z += a0 * v0.z + a1 * v1.z + a2 * v2.z + a3 * v3.z;
            acc.w += a0 * v0.w + a1 * v1.w + a2 * v2.w + a3 * v3.w;
        }
        for (; j < end; j++) {
            int s = d_csrc[j];
            float a = d_e[j];
            float4 v = *(const float4*)(h + (size_t)s * F + lane * 4);
            acc.x += a * v.x; acc.y += a * v.y; acc.z += a * v.z; acc.w += a * v.w;
        }
        const float4 bb = *(const float4*)(bias + lane * 4);
        float r0 = fmaxf(acc.x * inv + bb.x, 0.0f);
        float r1 = fmaxf(acc.y * inv + bb.y, 0.0f);
        float r2 = fmaxf(acc.z * inv + bb.z, 0.0f);
        float r3 = fmaxf(acc.w * inv + bb.w, 0.0f);
        if (DO_POOL) {
            int b;
            if (d_flag_b64) b = (int)((const long long*)batch)[w];
            else            b = ((const int*)batch)[w];
            red_add4(d_pool + (size_t)b * H2D + lane * 4, r0, r1, r2, r3);
        } else {
            *(float4*)(y + (size_t)w * F + lane * 4) = make_float4(r0, r1, r2, r3);
        }
    } else { // F == 64
        int sub = lane >> 4;
        int l2  = lane & 15;
        float4 acc = make_float4(0.f, 0.f, 0.f, 0.f);
        int j = beg + sub;
        for (; j + 2 < end; j += 4) {
            int s0 = d_csrc[j], s1 = d_csrc[j + 2];
            float a0 = d_e[j], a1 = d_e[j + 2];
            float4 v0 = *(const float4*)(h + (size_t)s0 * F + l2 * 4);
            float4 v1 = *(const float4*)(h + (size_t)s1 * F + l2 * 4);
            acc.x += a0 * v0.x + a1 * v1.x;
            acc.y += a0 * v0.y + a1 * v1.y;
            acc.z += a0 * v0.z + a1 * v1.z;
            acc.w += a0 * v0.w + a1 * v1.w;
        }
        for (; j < end; j += 2) {
            int s = d_csrc[j];
            float a = d_e[j];
            float4 v = *(const float4*)(h + (size_t)s * F + l2 * 4);
            acc.x += a * v.x; acc.y += a * v.y; acc.z += a * v.z; acc.w += a * v.w;
        }
        acc.x += __shfl_down_sync(0xFFFFFFFFu, acc.x, 16);
        acc.y += __shfl_down_sync(0xFFFFFFFFu, acc.y, 16);
        acc.z += __shfl_down_sync(0xFFFFFFFFu, acc.z, 16);
        acc.w += __shfl_down_sync(0xFFFFFFFFu, acc.w, 16);
        if (lane < 16) {
            const float4 bb = *(const float4*)(bias + l2 * 4);
            float4 r;
            r.x = fmaxf(acc.x * inv + bb.x, 0.0f);
            r.y = fmaxf(acc.y * inv + bb.y, 0.0f);
            r.z = fmaxf(acc.z * inv + bb.z, 0.0f);
            r.w = fmaxf(acc.w * inv + bb.w, 0.0f);
            *(float4*)(y + (size_t)w * F + l2 * 4) = r;
        }
    }
}

__global__ void counts_kernel(const void* batch, int N) {
    int n = blockIdx.x * blockDim.x + threadIdx.x;
    if (n >= N) return;
    int b;
    if (d_flag_b64) b = (int)((const long long*)batch)[n];
    else            b = ((const int*)batch)[n];
    atomicAdd(&d_cnt[b], 1.0f);
}

__global__ void fc_kernel(const float* __restrict__ Wfc, const float* __restrict__ bfc,
                          float* __restrict__ out) {
    __shared__ float p[H2D];
    int g = blockIdx.x;
    int f = threadIdx.x;
    float cnt = fmaxf(d_cnt[g], 1.0f);
    for (int k = f; k < H2D; k += 64) p[k] = d_pool[g * H2D + k] / cnt;
    __syncthreads();
    float acc = bfc[f];
    #pragma unroll 16
    for (int k = 0; k < H2D; k++) acc += p[k] * Wfc[k * 64 + f];
    out[g * 64 + f] = acc;
}

// ---------------- launch ----------------
static inline int cdiv(long long a, int b) { return (int)((a + b - 1) / b); }

extern "C" void kernel_launch(void* const* d_in, const int* in_sizes, int n_in,
                              void* d_out, int out_size) {
    const float* x      = (const float*)d_in[0];
    const void*  ei     = d_in[1];
    const void*  batch  = d_in[2];
    const float* W1     = (const float*)d_in[3];
    const float* a_src1 = (const float*)d_in[4];
    const float* a_dst1 = (const float*)d_in[5];
    const float* b1     = (const float*)d_in[6];
    const float* W2     = (const float*)d_in[7];
    const float* a_src2 = (const float*)d_in[8];
    const float* a_dst2 = (const float*)d_in[9];
    const float* b2     = (const float*)d_in[10];
    const float* Wfc    = (const float*)d_in[11];
    const float* bfc    = (const float*)d_in[12];
    float* out = (float*)d_out;

    const int N = in_sizes[2];
    const int E = in_sizes[1] / 2;
    const int B = cdiv(N, 1024);

    void *ppool, *pcnt;
    cudaGetSymbolAddress(&ppool, d_pool);
    cudaGetSymbolAddress(&pcnt, d_cnt);
    cudaMemsetAsync(ppool, 0, NG * H2D * sizeof(float), 0);
    cudaMemsetAsync(pcnt, 0, NG * sizeof(float), 0);

    detect_kernel<<<1, 128>>>(ei, batch, E, N);

    // CSR build
    init_deg_kernel<<<cdiv(N, 256), 256>>>(N);
    hist_kernel<<<cdiv(E, 256), 256>>>(ei, E);
    block_reduce_kernel<<<B, 256>>>(N);
    scan_bsum_kernel<<<1, 128>>>(B, N);
    block_scan_kernel<<<B, 256>>>(N);
    selfloop_kernel<<<cdiv(N, 256), 256>>>(N);
    scatter_kernel<<<cdiv(E, 256), 256>>>(ei, E);

    float *h1p, *y1p, *h2p;
    cudaGetSymbolAddress((void**)&h1p, d_h1);
    cudaGetSymbolAddress((void**)&y1p, d_y1);
    cudaGetSymbolAddress((void**)&h2p, d_h2);

    // ---- layer 1 ----
    gemm_tiled<ND, H1D><<<cdiv(N, 64), 256>>>(x, W1, h1p, a_src1, a_dst1, N);
    gat_kernel<H1D, 0><<<cdiv(N, 8), 256>>>(h1p, b1, y1p, batch, N);

    // ---- layer 2 ----
    gemm_tiled<H1D, H2D><<<cdiv(N, 64), 256>>>(y1p, W2, h2p, a_src2, a_dst2, N);
    gat_kernel<H2D, 1><<<cdiv(N, 8), 256>>>(h2p, b2, nullptr, batch, N);

    // ---- mean + fc ----
    counts_kernel<<<cdiv(N, 256), 256>>>(batch, N);
    fc_kernel<<<NG, 64>>>(Wfc, bfc, out);
}

// round 4
// speedup vs baseline: 2.6429x; 1.1164x over previous
#include <cuda_runtime.h>
#include <cuda_bf16.h>
#include <math.h>

#define ND   128
#define H1D  64
#define H2D  128
#define NG   64
#define MAXN 50000
#define MAXE 1600000
#define MAXET (MAXE + MAXN)
#define NEG_SLOPE 0.2f
#define NBLK 64

// ---------------- scratch ----------------
__device__ __align__(16) float d_h1[MAXN * H1D];
__device__ __align__(16) float d_y1[MAXN * H1D];
__device__ __align__(16) __nv_bfloat16 d_h2b[MAXN * H2D];   // bf16 layer-2 features
__device__ float d_as[MAXN];
__device__ float d_ad[MAXN];
__device__ float d_e[MAXET];
__device__ int   d_deg[MAXN];
__device__ int   d_cur[MAXN];
__device__ int   d_row[MAXN + 1];
__device__ int   d_csrc[MAXET];
__device__ int   d_bsum[NBLK];
__device__ int   d_bpre[NBLK];
__device__ __align__(16) float d_pool[NG * H2D];
__device__ float d_cnt[NG];
__device__ int   d_flag_e64;
__device__ int   d_flag_b64;

// ---------------- helpers ----------------
__device__ __forceinline__ void red_add4(float* p, float a, float b, float c, float d) {
    asm volatile("red.global.add.v4.f32 [%0], {%1,%2,%3,%4};"
                 :: "l"(p), "f"(a), "f"(b), "f"(c), "f"(d) : "memory");
}

__device__ __forceinline__ void load_edge(const void* ei, int i, int E, int is64, int& s, int& d) {
    if (is64) {
        const long long* p = (const long long*)ei;
        s = (int)p[i];
        d = (int)p[E + i];
    } else {
        const int* p = (const int*)ei;
        s = p[i];
        d = p[E + i];
    }
}

__device__ __forceinline__ int load_dst(const void* ei, int i, int E, int is64) {
    if (is64) return (int)((const long long*)ei)[E + i];
    return ((const int*)ei)[E + i];
}

// ---------------- dtype detection ----------------
__global__ void detect_kernel(const void* ei, const void* batch, int E, int N) {
    __shared__ int se, sb;
    int t = threadIdx.x;                // 128 threads
    if (t == 0) { se = 1; sb = 1; }
    __syncthreads();
    if (t < 64) {
        long long v = ((const long long*)ei)[t];
        if (v < 0 || v >= (long long)N) atomicAnd(&se, 0);
    } else {
        int base = N / 2 - 64;
        long long v = ((const long long*)batch)[base + (t - 64)];
        if (v < 0 || v >= NG) atomicAnd(&sb, 0);
    }
    __syncthreads();
    if (t == 0) { d_flag_e64 = se; d_flag_b64 = sb; }
}

// ---------------- CSR build ----------------
__global__ void init_deg_kernel(int N) {
    int i = blockIdx.x * blockDim.x + threadIdx.x;
    if (i < N) d_deg[i] = 1;
}

__global__ void hist_kernel(const void* ei, int E) {
    int i = blockIdx.x * blockDim.x + threadIdx.x;
    if (i >= E) return;
    int d = load_dst(ei, i, E, d_flag_e64);
    atomicAdd(&d_deg[d], 1);
}

__global__ void block_reduce_kernel(int N) {
    __shared__ int sm[256];
    int b = blockIdx.x, t = threadIdx.x;
    int base = b * 1024 + t * 4;
    int s = 0;
    #pragma unroll
    for (int k = 0; k < 4; k++) { int i = base + k; if (i < N) s += d_deg[i]; }
    sm[t] = s;
    __syncthreads();
    for (int off = 128; off; off >>= 1) {
        if (t < off) sm[t] += sm[t + off];
        __syncthreads();
    }
    if (t == 0) d_bsum[b] = sm[0];
}

__global__ void scan_bsum_kernel(int B, int N) {
    __shared__ int sm[128];
    int t = threadIdx.x;
    int v = (t < B) ? d_bsum[t] : 0;
    sm[t] = v;
    __syncthreads();
    for (int off = 1; off < 128; off <<= 1) {
        int u = (t >= off) ? sm[t - off] : 0;
        __syncthreads();
        sm[t] += u;
        __syncthreads();
    }
    if (t < B) d_bpre[t] = sm[t] - v;
    if (t == 127) d_row[N] = sm[127];
}

__global__ void block_scan_kernel(int N) {
    __shared__ int sm[256];
    int b = blockIdx.x, t = threadIdx.x;
    int base = b * 1024 + t * 4;
    int v[4], pre[4];
    int s = 0;
    #pragma unroll
    for (int k = 0; k < 4; k++) {
        int i = base + k;
        v[k] = (i < N) ? d_deg[i] : 0;
        pre[k] = s;
        s += v[k];
    }
    sm[t] = s;
    __syncthreads();
    for (int off = 1; off < 256; off <<= 1) {
        int u = (t >= off) ? sm[t - off] : 0;
        __syncthreads();
        sm[t] += u;
        __syncthreads();
    }
    int prefix = d_bpre[b] + (sm[t] - s);
    #pragma unroll
    for (int k = 0; k < 4; k++) {
        int i = base + k;
        if (i < N) d_row[i] = prefix + pre[k];
    }
}

__global__ void selfloop_kernel(int N) {
    int i = blockIdx.x * blockDim.x + threadIdx.x;
    if (i >= N) return;
    int p = d_row[i];
    d_csrc[p] = i;
    d_cur[i] = p + 1;
}

__global__ void scatter_kernel(const void* ei, int E) {
    int i = blockIdx.x * blockDim.x + threadIdx.x;
    if (i >= E) return;
    int is64 = d_flag_e64;
    int s, d;
    load_edge(ei, i, E, is64, s, d);
    int p = atomicAdd(&d_cur[d], 1);
    d_csrc[p] = s;
}

// ---------------- tiled GEMM with fused alphas ----------------
// BF16OUT: store C as bf16 (layer 2); alphas always from fp32 registers.
template <int K, int OUT, int BF16OUT>
__global__ void gemm_tiled(const float* __restrict__ A, const float* __restrict__ W,
                           float* __restrict__ C, __nv_bfloat16* __restrict__ Cb,
                           const float* __restrict__ avs, const float* __restrict__ avd,
                           int N) {
    const int CPT = OUT / 16;
    __shared__ float As[64][33];
    __shared__ float Ws[32][OUT];
    float acc[4][CPT];
    #pragma unroll
    for (int i = 0; i < 4; i++)
        #pragma unroll
        for (int j = 0; j < CPT; j++) acc[i][j] = 0.0f;

    int tx = threadIdx.x % 16, ty = threadIdx.x / 16;
    int row0 = blockIdx.x * 64;

    for (int kk = 0; kk < K; kk += 32) {
        for (int i = threadIdx.x; i < 64 * 32; i += 256) {
            int r = i / 32, c = i % 32;
            int gr = row0 + r;
            As[r][c] = (gr < N) ? A[(size_t)gr * K + kk + c] : 0.0f;
        }
        for (int i = threadIdx.x; i < 32 * OUT; i += 256) {
            int r = i / OUT, c = i % OUT;
            Ws[r][c] = W[(size_t)(kk + r) * OUT + c];
        }
        __syncthreads();
        #pragma unroll
        for (int k = 0; k < 32; k++) {
            float a[4], w[CPT];
            #pragma unroll
            for (int i = 0; i < 4; i++) a[i] = As[ty * 4 + i][k];
            #pragma unroll
            for (int j = 0; j < CPT; j++) w[j] = Ws[k][j * 16 + tx];
            #pragma unroll
            for (int i = 0; i < 4; i++)
                #pragma unroll
                for (int j = 0; j < CPT; j++) acc[i][j] += a[i] * w[j];
        }
        __syncthreads();
    }

    #pragma unroll
    for (int i = 0; i < 4; i++) {
        int r = row0 + ty * 4 + i;
        if (r >= N) break;
        #pragma unroll
        for (int j = 0; j < CPT; j++) {
            if (BF16OUT) Cb[(size_t)r * OUT + j * 16 + tx] = __float2bfloat16(acc[i][j]);
            else         C[(size_t)r * OUT + j * 16 + tx] = acc[i][j];
        }
    }

    float vs[CPT], vd[CPT];
    #pragma unroll
    for (int j = 0; j < CPT; j++) {
        vs[j] = avs[j * 16 + tx];
        vd[j] = avd[j * 16 + tx];
    }
    #pragma unroll
    for (int i = 0; i < 4; i++) {
        float ps = 0.0f, pd = 0.0f;
        #pragma unroll
        for (int j = 0; j < CPT; j++) {
            ps += acc[i][j] * vs[j];
            pd += acc[i][j] * vd[j];
        }
        #pragma unroll
        for (int o = 8; o; o >>= 1) {
            ps += __shfl_xor_sync(0xFFFFFFFFu, ps, o);
            pd += __shfl_xor_sync(0xFFFFFFFFu, pd, o);
        }
        int r = row0 + ty * 4 + i;
        if (tx == 0 && r < N) { d_as[r] = ps; d_ad[r] = pd; }
    }
}

// ---------------- softmax prologue shared by both gat kernels ----------------
__device__ __forceinline__ float gat_softmax(int beg, int end, int lane, float ad_d) {
    float m = -INFINITY;
    for (int j = beg + lane; j < end; j += 32) {
        int s = d_csrc[j];
        float e = d_as[s] + ad_d;
        e = (e > 0.0f) ? e : NEG_SLOPE * e;
        d_e[j] = e;
        m = fmaxf(m, e);
    }
    #pragma unroll
    for (int o = 16; o; o >>= 1) m = fmaxf(m, __shfl_xor_sync(0xFFFFFFFFu, m, o));
    float den = 0.0f;
    for (int j = beg + lane; j < end; j += 32) {
        float ex = __expf(d_e[j] - m);
        d_e[j] = ex;
        den += ex;
    }
    #pragma unroll
    for (int o = 16; o; o >>= 1) den += __shfl_xor_sync(0xFFFFFFFFu, den, o);
    return 1.0f / (den + 1e-16f);
}

// ---------------- layer-1 aggregation (fp32, F=64) ----------------
__global__ void gat1_kernel(const float* __restrict__ h, const float* __restrict__ bias,
                            float* __restrict__ y, int N) {
    int w = (blockIdx.x * blockDim.x + threadIdx.x) >> 5;
    int lane = threadIdx.x & 31;
    if (w >= N) return;
    int beg = d_row[w], end = d_row[w + 1];
    float inv = gat_softmax(beg, end, lane, d_ad[w]);

    int sub = lane >> 4;
    int l2  = lane & 15;
    float4 acc = make_float4(0.f, 0.f, 0.f, 0.f);
    int j = beg + sub;
    for (; j + 2 < end; j += 4) {
        int s0 = d_csrc[j], s1 = d_csrc[j + 2];
        float a0 = d_e[j], a1 = d_e[j + 2];
        float4 v0 = *(const float4*)(h + (size_t)s0 * H1D + l2 * 4);
        float4 v1 = *(const float4*)(h + (size_t)s1 * H1D + l2 * 4);
        acc.x += a0 * v0.x + a1 * v1.x;
        acc.y += a0 * v0.y + a1 * v1.y;
        acc.z += a0 * v0.z + a1 * v1.z;
        acc.w += a0 * v0.w + a1 * v1.w;
    }
    for (; j < end; j += 2) {
        int s = d_csrc[j];
        float a = d_e[j];
        float4 v = *(const float4*)(h + (size_t)s * H1D + l2 * 4);
        acc.x += a * v.x; acc.y += a * v.y; acc.z += a * v.z; acc.w += a * v.w;
    }
    acc.x += __shfl_down_sync(0xFFFFFFFFu, acc.x, 16);
    acc.y += __shfl_down_sync(0xFFFFFFFFu, acc.y, 16);
    acc.z += __shfl_down_sync(0xFFFFFFFFu, acc.z, 16);
    acc.w += __shfl_down_sync(0xFFFFFFFFu, acc.w, 16);
    if (lane < 16) {
        const float4 bb = *(const float4*)(bias + l2 * 4);
        float4 r;
        r.x = fmaxf(acc.x * inv + bb.x, 0.0f);
        r.y = fmaxf(acc.y * inv + bb.y, 0.0f);
        r.z = fmaxf(acc.z * inv + bb.z, 0.0f);
        r.w = fmaxf(acc.w * inv + bb.w, 0.0f);
        *(float4*)(y + (size_t)w * H1D + l2 * 4) = r;
    }
}

// ---------------- layer-2 aggregation (bf16 gather, F=128) + pool ------------
__device__ __forceinline__ void bf16x4(uint2 u, float& f0, float& f1, float& f2, float& f3) {
    f0 = __uint_as_float(u.x << 16);
    f1 = __uint_as_float(u.x & 0xFFFF0000u);
    f2 = __uint_as_float(u.y << 16);
    f3 = __uint_as_float(u.y & 0xFFFF0000u);
}

__global__ void gat2_kernel(const __nv_bfloat16* __restrict__ h, const float* __restrict__ bias,
                            const void* batch, int N) {
    int w = (blockIdx.x * blockDim.x + threadIdx.x) >> 5;
    int lane = threadIdx.x & 31;
    if (w >= N) return;
    int beg = d_row[w], end = d_row[w + 1];
    float inv = gat_softmax(beg, end, lane, d_ad[w]);

    float4 acc = make_float4(0.f, 0.f, 0.f, 0.f);
    int j = beg;
    for (; j + 4 <= end; j += 4) {
        int s0 = d_csrc[j], s1 = d_csrc[j + 1], s2 = d_csrc[j + 2], s3 = d_csrc[j + 3];
        float a0 = d_e[j], a1 = d_e[j + 1], a2 = d_e[j + 2], a3 = d_e[j + 3];
        uint2 u0 = *((const uint2*)(h + (size_t)s0 * H2D) + lane);
        uint2 u1 = *((const uint2*)(h + (size_t)s1 * H2D) + lane);
        uint2 u2 = *((const uint2*)(h + (size_t)s2 * H2D) + lane);
        uint2 u3 = *((const uint2*)(h + (size_t)s3 * H2D) + lane);
        float x0, x1, x2, x3;
        bf16x4(u0, x0, x1, x2, x3);
        acc.x += a0 * x0; acc.y += a0 * x1; acc.z += a0 * x2; acc.w += a0 * x3;
        bf16x4(u1, x0, x1, x2, x3);
        acc.x += a1 * x0; acc.y += a1 * x1; acc.z += a1 * x2; acc.w += a1 * x3;
        bf16x4(u2, x0, x1, x2, x3);
        acc.x += a2 * x0; acc.y += a2 * x1; acc.z += a2 * x2; acc.w += a2 * x3;
        bf16x4(u3, x0, x1, x2, x3);
        acc.x += a3 * x0; acc.y += a3 * x1; acc.z += a3 * x2; acc.w += a3 * x3;
    }
    for (; j < end; j++) {
        int s = d_csrc[j];
        float a = d_e[j];
        uint2 u = *((const uint2*)(h + (size_t)s * H2D) + lane);
        float x0, x1, x2, x3;
        bf16x4(u, x0, x1, x2, x3);
        acc.x += a * x0; acc.y += a * x1; acc.z += a * x2; acc.w += a * x3;
    }
    const float4 bb = *(const float4*)(bias + lane * 4);
    float r0 = fmaxf(acc.x * inv + bb.x, 0.0f);
    float r1 = fmaxf(acc.y * inv + bb.y, 0.0f);
    float r2 = fmaxf(acc.z * inv + bb.z, 0.0f);
    float r3 = fmaxf(acc.w * inv + bb.w, 0.0f);
    int b;
    if (d_flag_b64) b = (int)((const long long*)batch)[w];
    else            b = ((const int*)batch)[w];
    red_add4(d_pool + (size_t)b * H2D + lane * 4, r0, r1, r2, r3);
}

__global__ void counts_kernel(const void* batch, int N) {
    int n = blockIdx.x * blockDim.x + threadIdx.x;
    if (n >= N) return;
    int b;
    if (d_flag_b64) b = (int)((const long long*)batch)[n];
    else            b = ((const int*)batch)[n];
    atomicAdd(&d_cnt[b], 1.0f);
}

__global__ void fc_kernel(const float* __restrict__ Wfc, const float* __restrict__ bfc,
                          float* __restrict__ out) {
    __shared__ float p[H2D];
    int g = blockIdx.x;
    int f = threadIdx.x;
    float cnt = fmaxf(d_cnt[g], 1.0f);
    for (int k = f; k < H2D; k += 64) p[k] = d_pool[g * H2D + k] / cnt;
    __syncthreads();
    float acc = bfc[f];
    #pragma unroll 16
    for (int k = 0; k < H2D; k++) acc += p[k] * Wfc[k * 64 + f];
    out[g * 64 + f] = acc;
}

// ---------------- launch ----------------
static inline int cdiv(long long a, int b) { return (int)((a + b - 1) / b); }

extern "C" void kernel_launch(void* const* d_in, const int* in_sizes, int n_in,
                              void* d_out, int out_size) {
    const float* x      = (const float*)d_in[0];
    const void*  ei     = d_in[1];
    const void*  batch  = d_in[2];
    const float* W1     = (const float*)d_in[3];
    const float* a_src1 = (const float*)d_in[4];
    const float* a_dst1 = (const float*)d_in[5];
    const float* b1     = (const float*)d_in[6];
    const float* W2     = (const float*)d_in[7];
    const float* a_src2 = (const float*)d_in[8];
    const float* a_dst2 = (const float*)d_in[9];
    const float* b2     = (const float*)d_in[10];
    const float* Wfc    = (const float*)d_in[11];
    const float* bfc    = (const float*)d_in[12];
    float* out = (float*)d_out;

    const int N = in_sizes[2];
    const int E = in_sizes[1] / 2;
    const int B = cdiv(N, 1024);

    // one-time side-stream setup (host resources only; identical GPU work per call)
    static cudaStream_t s2 = nullptr;
    static cudaEvent_t ev0 = nullptr, evA = nullptr;
    if (!s2) {
        if (cudaStreamCreateWithFlags(&s2, cudaStreamNonBlocking) != cudaSuccess) s2 = nullptr;
        cudaEventCreateWithFlags(&ev0, cudaEventDisableTiming);
        cudaEventCreateWithFlags(&evA, cudaEventDisableTiming);
    }
    const bool fork = (s2 != nullptr);
    cudaStream_t sb = fork ? s2 : (cudaStream_t)0;

    void *ppool, *pcnt;
    cudaGetSymbolAddress(&ppool, d_pool);
    cudaGetSymbolAddress(&pcnt, d_cnt);
    cudaMemsetAsync(ppool, 0, NG * H2D * sizeof(float), 0);
    cudaMemsetAsync(pcnt, 0, NG * sizeof(float), 0);

    init_deg_kernel<<<cdiv(N, 256), 256, 0, 0>>>(N);
    detect_kernel<<<1, 128, 0, 0>>>(ei, batch, E, N);

    float *h1p, *y1p;
    __nv_bfloat16 *h2p;
    cudaGetSymbolAddress((void**)&h1p, d_h1);
    cudaGetSymbolAddress((void**)&y1p, d_y1);
    cudaGetSymbolAddress((void**)&h2p, d_h2b);

    // fork: side stream does GEMM1 + counts while main stream builds CSR
    if (fork) {
        cudaEventRecord(ev0, 0);
        cudaStreamWaitEvent(sb, ev0, 0);
    }
    gemm_tiled<ND, H1D, 0><<<cdiv(N, 64), 256, 0, sb>>>(x, W1, h1p, nullptr, a_src1, a_dst1, N);
    counts_kernel<<<cdiv(N, 256), 256, 0, sb>>>(batch, N);
    if (fork) cudaEventRecord(evA, sb);

    // main stream: CSR build
    hist_kernel<<<cdiv(E, 256), 256, 0, 0>>>(ei, E);
    block_reduce_kernel<<<B, 256, 0, 0>>>(N);
    scan_bsum_kernel<<<1, 128, 0, 0>>>(B, N);
    block_scan_kernel<<<B, 256, 0, 0>>>(N);
    selfloop_kernel<<<cdiv(N, 256), 256, 0, 0>>>(N);
    scatter_kernel<<<cdiv(E, 256), 256, 0, 0>>>(ei, E);

    if (fork) cudaStreamWaitEvent(0, evA, 0);

    // layer 1
    gat1_kernel<<<cdiv(N, 8), 256, 0, 0>>>(h1p, b1, y1p, N);
    // layer 2 (bf16 features for the gather)
    gemm_tiled<H1D, H2D, 1><<<cdiv(N, 64), 256, 0, 0>>>(y1p, W2, nullptr, h2p, a_src2, a_dst2, N);
    gat2_kernel<<<cdiv(N, 8), 256, 0, 0>>>(h2p, b2, batch, N);

    fc_kernel<<<NG, 64, 0, 0>>>(Wfc, bfc, out);
}

// round 5
// speedup vs baseline: 3.1337x; 1.1857x over previous
#include <cuda_runtime.h>
#include <cuda_bf16.h>
#include <math.h>

#define ND   128
#define H1D  64
#define H2D  128
#define NG   64
#define MAXN 50000
#define MAXE 1600000
#define MAXET (MAXE + MAXN)
#define NEG_SLOPE 0.2f
#define NBLK 64

// ---------------- scratch ----------------
__device__ __align__(16) __nv_bfloat16 d_h1b[MAXN * H1D];   // bf16 layer-1 features
__device__ __align__(16) float d_y1[MAXN * H1D];
__device__ __align__(16) __nv_bfloat16 d_h2b[MAXN * H2D];   // bf16 layer-2 features
__device__ float d_as[MAXN];
__device__ float d_ad[MAXN];
__device__ float d_e[MAXET];
__device__ int   d_deg[MAXN];
__device__ int   d_cur[MAXN];
__device__ int   d_row[MAXN + 1];
__device__ int   d_csrc[MAXET];
__device__ int   d_bsum[NBLK];
__device__ int   d_bpre[NBLK];
__device__ __align__(16) float d_pool[NG * H2D];
__device__ float d_cnt[NG];
__device__ int   d_flag_e64;
__device__ int   d_flag_b64;

// ---------------- helpers ----------------
__device__ __forceinline__ void red_add4(float* p, float a, float b, float c, float d) {
    asm volatile("red.global.add.v4.f32 [%0], {%1,%2,%3,%4};"
                 :: "l"(p), "f"(a), "f"(b), "f"(c), "f"(d) : "memory");
}

__device__ __forceinline__ void load_edge(const void* ei, int i, int E, int is64, int& s, int& d) {
    if (is64) {
        const long long* p = (const long long*)ei;
        s = (int)p[i];
        d = (int)p[E + i];
    } else {
        const int* p = (const int*)ei;
        s = p[i];
        d = p[E + i];
    }
}

__device__ __forceinline__ int load_dst(const void* ei, int i, int E, int is64) {
    if (is64) return (int)((const long long*)ei)[E + i];
    return ((const int*)ei)[E + i];
}

// ---------------- dtype detection ----------------
__global__ void detect_kernel(const void* ei, const void* batch, int E, int N) {
    __shared__ int se, sb;
    int t = threadIdx.x;                // 128 threads
    if (t == 0) { se = 1; sb = 1; }
    __syncthreads();
    if (t < 64) {
        long long v = ((const long long*)ei)[t];
        if (v < 0 || v >= (long long)N) atomicAnd(&se, 0);
    } else {
        int base = N / 2 - 64;
        long long v = ((const long long*)batch)[base + (t - 64)];
        if (v < 0 || v >= NG) atomicAnd(&sb, 0);
    }
    __syncthreads();
    if (t == 0) { d_flag_e64 = se; d_flag_b64 = sb; }
}

// ---------------- CSR build (self-loop folded into scan: row = scan(deg)+i) --
__global__ void hist_kernel(const void* ei, int E) {
    int i = blockIdx.x * blockDim.x + threadIdx.x;
    if (i >= E) return;
    int d = load_dst(ei, i, E, d_flag_e64);
    atomicAdd(&d_deg[d], 1);
}

__global__ void block_reduce_kernel(int N) {
    __shared__ int sm[256];
    int b = blockIdx.x, t = threadIdx.x;
    int base = b * 1024 + t * 4;
    int s = 0;
    #pragma unroll
    for (int k = 0; k < 4; k++) { int i = base + k; if (i < N) s += d_deg[i]; }
    sm[t] = s;
    __syncthreads();
    for (int off = 128; off; off >>= 1) {
        if (t < off) sm[t] += sm[t + off];
        __syncthreads();
    }
    if (t == 0) d_bsum[b] = sm[0];
}

__global__ void scan_bsum_kernel(int B, int N) {
    __shared__ int sm[128];
    int t = threadIdx.x;
    int v = (t < B) ? d_bsum[t] : 0;
    sm[t] = v;
    __syncthreads();
    for (int off = 1; off < 128; off <<= 1) {
        int u = (t >= off) ? sm[t - off] : 0;
        __syncthreads();
        sm[t] += u;
        __syncthreads();
    }
    if (t < B) d_bpre[t] = sm[t] - v;
    if (t == 127) d_row[N] = sm[127] + N;   // +N self loops
}

__global__ void block_scan_kernel(int N) {
    __shared__ int sm[256];
    int b = blockIdx.x, t = threadIdx.x;
    int base = b * 1024 + t * 4;
    int v[4], pre[4];
    int s = 0;
    #pragma unroll
    for (int k = 0; k < 4; k++) {
        int i = base + k;
        v[k] = (i < N) ? d_deg[i] : 0;
        pre[k] = s;
        s += v[k];
    }
    sm[t] = s;
    __syncthreads();
    for (int off = 1; off < 256; off <<= 1) {
        int u = (t >= off) ? sm[t - off] : 0;
        __syncthreads();
        sm[t] += u;
        __syncthreads();
    }
    int prefix = d_bpre[b] + (sm[t] - s);
    #pragma unroll
    for (int k = 0; k < 4; k++) {
        int i = base + k;
        if (i < N) d_row[i] = prefix + pre[k] + i;   // +i self loops before i
    }
}

__global__ void selfloop_kernel(int N) {
    int i = blockIdx.x * blockDim.x + threadIdx.x;
    if (i >= N) return;
    int p = d_row[i];
    d_csrc[p] = i;
    d_cur[i] = p + 1;
}

__global__ void scatter_kernel(const void* ei, int E) {
    int i = blockIdx.x * blockDim.x + threadIdx.x;
    if (i >= E) return;
    int is64 = d_flag_e64;
    int s, d;
    load_edge(ei, i, E, is64, s, d);
    int p = atomicAdd(&d_cur[d], 1);
    d_csrc[p] = s;
}

// ---------------- tiled GEMM with fused alphas, bf16 feature output ---------
template <int K, int OUT>
__global__ void gemm_tiled(const float* __restrict__ A, const float* __restrict__ W,
                           __nv_bfloat16* __restrict__ Cb,
                           const float* __restrict__ avs, const float* __restrict__ avd,
                           int N) {
    const int CPT = OUT / 16;
    __shared__ float As[64][33];
    __shared__ float Ws[32][OUT];
    float acc[4][CPT];
    #pragma unroll
    for (int i = 0; i < 4; i++)
        #pragma unroll
        for (int j = 0; j < CPT; j++) acc[i][j] = 0.0f;

    int tx = threadIdx.x % 16, ty = threadIdx.x / 16;
    int row0 = blockIdx.x * 64;

    for (int kk = 0; kk < K; kk += 32) {
        for (int i = threadIdx.x; i < 64 * 32; i += 256) {
            int r = i / 32, c = i % 32;
            int gr = row0 + r;
            As[r][c] = (gr < N) ? A[(size_t)gr * K + kk + c] : 0.0f;
        }
        for (int i = threadIdx.x; i < 32 * OUT; i += 256) {
            int r = i / OUT, c = i % OUT;
            Ws[r][c] = W[(size_t)(kk + r) * OUT + c];
        }
        __syncthreads();
        #pragma unroll
        for (int k = 0; k < 32; k++) {
            float a[4], w[CPT];
            #pragma unroll
            for (int i = 0; i < 4; i++) a[i] = As[ty * 4 + i][k];
            #pragma unroll
            for (int j = 0; j < CPT; j++) w[j] = Ws[k][j * 16 + tx];
            #pragma unroll
            for (int i = 0; i < 4; i++)
                #pragma unroll
                for (int j = 0; j < CPT; j++) acc[i][j] += a[i] * w[j];
        }
        __syncthreads();
    }

    #pragma unroll
    for (int i = 0; i < 4; i++) {
        int r = row0 + ty * 4 + i;
        if (r >= N) break;
        #pragma unroll
        for (int j = 0; j < CPT; j++)
            Cb[(size_t)r * OUT + j * 16 + tx] = __float2bfloat16(acc[i][j]);
    }

    float vs[CPT], vd[CPT];
    #pragma unroll
    for (int j = 0; j < CPT; j++) {
        vs[j] = avs[j * 16 + tx];
        vd[j] = avd[j * 16 + tx];
    }
    #pragma unroll
    for (int i = 0; i < 4; i++) {
        float ps = 0.0f, pd = 0.0f;
        #pragma unroll
        for (int j = 0; j < CPT; j++) {
            ps += acc[i][j] * vs[j];
            pd += acc[i][j] * vd[j];
        }
        #pragma unroll
        for (int o = 8; o; o >>= 1) {
            ps += __shfl_xor_sync(0xFFFFFFFFu, ps, o);
            pd += __shfl_xor_sync(0xFFFFFFFFu, pd, o);
        }
        int r = row0 + ty * 4 + i;
        if (tx == 0 && r < N) { d_as[r] = ps; d_ad[r] = pd; }
    }
}

// ---------------- softmax prologue ----------------
__device__ __forceinline__ float gat_softmax(int beg, int end, int lane, float ad_d) {
    float m = -INFINITY;
    for (int j = beg + lane; j < end; j += 32) {
        int s = d_csrc[j];
        float e = d_as[s] + ad_d;
        e = (e > 0.0f) ? e : NEG_SLOPE * e;
        d_e[j] = e;
        m = fmaxf(m, e);
    }
    #pragma unroll
    for (int o = 16; o; o >>= 1) m = fmaxf(m, __shfl_xor_sync(0xFFFFFFFFu, m, o));
    float den = 0.0f;
    for (int j = beg + lane; j < end; j += 32) {
        float ex = __expf(d_e[j] - m);
        d_e[j] = ex;
        den += ex;
    }
    #pragma unroll
    for (int o = 16; o; o >>= 1) den += __shfl_xor_sync(0xFFFFFFFFu, den, o);
    return 1.0f / (den + 1e-16f);
}

__device__ __forceinline__ void bf16x2u(unsigned u, float& f0, float& f1) {
    f0 = __uint_as_float(u << 16);
    f1 = __uint_as_float(u & 0xFFFF0000u);
}

// ---------------- layer-1 aggregation (bf16 gather, F=64) -------------------
__global__ void gat1_kernel(const __nv_bfloat16* __restrict__ h, const float* __restrict__ bias,
                            float* __restrict__ y, int N) {
    int w = (blockIdx.x * blockDim.x + threadIdx.x) >> 5;
    int lane = threadIdx.x & 31;
    if (w >= N) return;
    int beg = d_row[w], end = d_row[w + 1];
    float inv = gat_softmax(beg, end, lane, d_ad[w]);

    float ax = 0.0f, ay = 0.0f;
    int j = beg;
    for (; j + 4 <= end; j += 4) {
        int s0 = d_csrc[j], s1 = d_csrc[j + 1], s2 = d_csrc[j + 2], s3 = d_csrc[j + 3];
        float a0 = d_e[j], a1 = d_e[j + 1], a2 = d_e[j + 2], a3 = d_e[j + 3];
        unsigned u0 = *((const unsigned*)(h + (size_t)s0 * H1D) + lane);
        unsigned u1 = *((const unsigned*)(h + (size_t)s1 * H1D) + lane);
        unsigned u2 = *((const unsigned*)(h + (size_t)s2 * H1D) + lane);
        unsigned u3 = *((const unsigned*)(h + (size_t)s3 * H1D) + lane);
        float x0, x1;
        bf16x2u(u0, x0, x1); ax += a0 * x0; ay += a0 * x1;
        bf16x2u(u1, x0, x1); ax += a1 * x0; ay += a1 * x1;
        bf16x2u(u2, x0, x1); ax += a2 * x0; ay += a2 * x1;
        bf16x2u(u3, x0, x1); ax += a3 * x0; ay += a3 * x1;
    }
    for (; j < end; j++) {
        int s = d_csrc[j];
        float a = d_e[j];
        unsigned u = *((const unsigned*)(h + (size_t)s * H1D) + lane);
        float x0, x1;
        bf16x2u(u, x0, x1); ax += a * x0; ay += a * x1;
    }
    const float2 bb = *(const float2*)(bias + lane * 2);
    float2 r;
    r.x = fmaxf(ax * inv + bb.x, 0.0f);
    r.y = fmaxf(ay * inv + bb.y, 0.0f);
    *(float2*)(y + (size_t)w * H1D + lane * 2) = r;
}

// ---------------- layer-2 aggregation (bf16 gather, F=128) + pool -----------
__device__ __forceinline__ void bf16x4(uint2 u, float& f0, float& f1, float& f2, float& f3) {
    f0 = __uint_as_float(u.x << 16);
    f1 = __uint_as_float(u.x & 0xFFFF0000u);
    f2 = __uint_as_float(u.y << 16);
    f3 = __uint_as_float(u.y & 0xFFFF0000u);
}

__global__ void gat2_kernel(const __nv_bfloat16* __restrict__ h, const float* __restrict__ bias,
                            const void* batch, int N) {
    int w = (blockIdx.x * blockDim.x + threadIdx.x) >> 5;
    int lane = threadIdx.x & 31;
    if (w >= N) return;
    int beg = d_row[w], end = d_row[w + 1];
    float inv = gat_softmax(beg, end, lane, d_ad[w]);

    float4 acc = make_float4(0.f, 0.f, 0.f, 0.f);
    int j = beg;
    for (; j + 4 <= end; j += 4) {
        int s0 = d_csrc[j], s1 = d_csrc[j + 1], s2 = d_csrc[j + 2], s3 = d_csrc[j + 3];
        float a0 = d_e[j], a1 = d_e[j + 1], a2 = d_e[j + 2], a3 = d_e[j + 3];
        uint2 u0 = *((const uint2*)(h + (size_t)s0 * H2D) + lane);
        uint2 u1 = *((const uint2*)(h + (size_t)s1 * H2D) + lane);
        uint2 u2 = *((const uint2*)(h + (size_t)s2 * H2D) + lane);
        uint2 u3 = *((const uint2*)(h + (size_t)s3 * H2D) + lane);
        float x0, x1, x2, x3;
        bf16x4(u0, x0, x1, x2, x3);
        acc.x += a0 * x0; acc.y += a0 * x1; acc.z += a0 * x2; acc.w += a0 * x3;
        bf16x4(u1, x0, x1, x2, x3);
        acc.x += a1 * x0; acc.y += a1 * x1; acc.z += a1 * x2; acc.w += a1 * x3;
        bf16x4(u2, x0, x1, x2, x3);
        acc.x += a2 * x0; acc.y += a2 * x1; acc.z += a2 * x2; acc.w += a2 * x3;
        bf16x4(u3, x0, x1, x2, x3);
        acc.x += a3 * x0; acc.y += a3 * x1; acc.z += a3 * x2; acc.w += a3 * x3;
    }
    for (; j < end; j++) {
        int s = d_csrc[j];
        float a = d_e[j];
        uint2 u = *((const uint2*)(h + (size_t)s * H2D) + lane);
        float x0, x1, x2, x3;
        bf16x4(u, x0, x1, x2, x3);
        acc.x += a * x0; acc.y += a * x1; acc.z += a * x2; acc.w += a * x3;
    }
    const float4 bb = *(const float4*)(bias + lane * 4);
    float r0 = fmaxf(acc.x * inv + bb.x, 0.0f);
    float r1 = fmaxf(acc.y * inv + bb.y, 0.0f);
    float r2 = fmaxf(acc.z * inv + bb.z, 0.0f);
    float r3 = fmaxf(acc.w * inv + bb.w, 0.0f);
    int b;
    if (d_flag_b64) b = (int)((const long long*)batch)[w];
    else            b = ((const int*)batch)[w];
    red_add4(d_pool + (size_t)b * H2D + lane * 4, r0, r1, r2, r3);
}

// ---------------- counts: warp-aggregated atomics ----------------
__global__ void counts_kernel(const void* batch, int N) {
    int n = blockIdx.x * blockDim.x + threadIdx.x;
    unsigned mask = __ballot_sync(0xFFFFFFFFu, n < N);
    if (n >= N) return;
    int b;
    if (d_flag_b64) b = (int)((const long long*)batch)[n];
    else            b = ((const int*)batch)[n];
    unsigned peers = __match_any_sync(mask, b);
    int leader = __ffs(peers) - 1;
    if ((threadIdx.x & 31) == leader)
        atomicAdd(&d_cnt[b], (float)__popc(peers));
}

__global__ void fc_kernel(const float* __restrict__ Wfc, const float* __restrict__ bfc,
                          float* __restrict__ out) {
    __shared__ float p[H2D];
    int g = blockIdx.x;
    int f = threadIdx.x;
    float cnt = fmaxf(d_cnt[g], 1.0f);
    for (int k = f; k < H2D; k += 64) p[k] = d_pool[g * H2D + k] / cnt;
    __syncthreads();
    float acc = bfc[f];
    #pragma unroll 16
    for (int k = 0; k < H2D; k++) acc += p[k] * Wfc[k * 64 + f];
    out[g * 64 + f] = acc;
}

// ---------------- launch ----------------
static inline int cdiv(long long a, int b) { return (int)((a + b - 1) / b); }

extern "C" void kernel_launch(void* const* d_in, const int* in_sizes, int n_in,
                              void* d_out, int out_size) {
    const float* x      = (const float*)d_in[0];
    const void*  ei     = d_in[1];
    const void*  batch  = d_in[2];
    const float* W1     = (const float*)d_in[3];
    const float* a_src1 = (const float*)d_in[4];
    const float* a_dst1 = (const float*)d_in[5];
    const float* b1     = (const float*)d_in[6];
    const float* W2     = (const float*)d_in[7];
    const float* a_src2 = (const float*)d_in[8];
    const float* a_dst2 = (const float*)d_in[9];
    const float* b2     = (const float*)d_in[10];
    const float* Wfc    = (const float*)d_in[11];
    const float* bfc    = (const float*)d_in[12];
    float* out = (float*)d_out;

    const int N = in_sizes[2];
    const int E = in_sizes[1] / 2;
    const int B = cdiv(N, 1024);

    static cudaStream_t s2 = nullptr;
    static cudaEvent_t ev0 = nullptr, evA = nullptr;
    if (!s2) {
        if (cudaStreamCreateWithFlags(&s2, cudaStreamNonBlocking) != cudaSuccess) s2 = nullptr;
        cudaEventCreateWithFlags(&ev0, cudaEventDisableTiming);
        cudaEventCreateWithFlags(&evA, cudaEventDisableTiming);
    }
    const bool fork = (s2 != nullptr);
    cudaStream_t sb = fork ? s2 : (cudaStream_t)0;

    void *ppool, *pcnt, *pdeg;
    cudaGetSymbolAddress(&ppool, d_pool);
    cudaGetSymbolAddress(&pcnt, d_cnt);
    cudaGetSymbolAddress(&pdeg, d_deg);
    cudaMemsetAsync(ppool, 0, NG * H2D * sizeof(float), 0);
    cudaMemsetAsync(pcnt, 0, NG * sizeof(float), 0);
    cudaMemsetAsync(pdeg, 0, (size_t)N * sizeof(int), 0);

    detect_kernel<<<1, 128, 0, 0>>>(ei, batch, E, N);

    __nv_bfloat16 *h1p, *h2p;
    float *y1p;
    cudaGetSymbolAddress((void**)&h1p, d_h1b);
    cudaGetSymbolAddress((void**)&y1p, d_y1);
    cudaGetSymbolAddress((void**)&h2p, d_h2b);

    // fork: side stream does counts + GEMM1 while main stream builds CSR
    if (fork) {
        cudaEventRecord(ev0, 0);
        cudaStreamWaitEvent(sb, ev0, 0);
    }
    counts_kernel<<<cdiv(N, 256), 256, 0, sb>>>(batch, N);
    gemm_tiled<ND, H1D><<<cdiv(N, 64), 256, 0, sb>>>(x, W1, h1p, a_src1, a_dst1, N);
    if (fork) cudaEventRecord(evA, sb);

    // main stream: CSR build
    hist_kernel<<<cdiv(E, 256), 256, 0, 0>>>(ei, E);
    block_reduce_kernel<<<B, 256, 0, 0>>>(N);
    scan_bsum_kernel<<<1, 128, 0, 0>>>(B, N);
    block_scan_kernel<<<B, 256, 0, 0>>>(N);
    selfloop_kernel<<<cdiv(N, 256), 256, 0, 0>>>(N);
    scatter_kernel<<<cdiv(E, 256), 256, 0, 0>>>(ei, E);

    if (fork) cudaStreamWaitEvent(0, evA, 0);

    gat1_kernel<<<cdiv(N, 8), 256, 0, 0>>>(h1p, b1, y1p, N);
    gemm_tiled<H1D, H2D><<<cdiv(N, 64), 256, 0, 0>>>(y1p, W2, h2p, a_src2, a_dst2, N);
    gat2_kernel<<<cdiv(N, 8), 256, 0, 0>>>(h2p, b2, batch, N);

    fc_kernel<<<NG, 64, 0, 0>>>(Wfc, bfc, out);
}